// round 3
// baseline (speedup 1.0000x reference)
#include <cuda_runtime.h>
#include <cuda_bf16.h>
#include <float.h>

#define BS 16
#define SEQ 512
#define VOCAB 32000
#define NMASK 80
#define NITEMS (BS * NMASK)
#define THREADS 256

// Scratch (no device allocation allowed in kernel_launch)
__device__ int   g_pos[NITEMS];       // masked positions, row-major (b, j)
__device__ float g_logp[NITEMS];      // log-prob at target per item
__device__ int   g_corr[NITEMS];      // 1 if argmax == target
__device__ int   g_mask_is_byte;      // 1 if mask stored as 1-byte bool
__device__ int   g_tgt_is_i64;        // 1 if target stored as int64

// ---------------------------------------------------------------------------
// Kernel 0: detect storage layout of mask and target (deterministic).
// ---------------------------------------------------------------------------
__global__ void detect_kernel(const unsigned char* __restrict__ mask,
                              const int* __restrict__ target) {
    const int tid = threadIdx.x;
    __shared__ int s_byte_flag;   // found nonzero byte at offset %4 != 0
    __shared__ int s_odd_nonzero; // found nonzero odd int32 word in target
    if (tid == 0) { s_byte_flag = 0; s_odd_nonzero = 0; }
    __syncthreads();

    // mask: safe to read 2048 bytes under either layout (8KB or 32KB buffer)
    for (int i = tid; i < 2048; i += blockDim.x) {
        if ((i & 3) != 0 && mask[i] != 0) atomicOr(&s_byte_flag, 1);
    }
    // target: safe to read 256 int32 words under either layout (1280 or 2560 words)
    for (int i = tid; i < 128; i += blockDim.x) {
        if (target[2 * i + 1] != 0) atomicOr(&s_odd_nonzero, 1);
    }
    __syncthreads();
    if (tid == 0) {
        g_mask_is_byte = s_byte_flag;
        g_tgt_is_i64   = s_odd_nonzero ? 0 : 1;
    }
}

// ---------------------------------------------------------------------------
// Kernel 1: recover masked positions per batch row (stable, ascending order —
// matches stable argsort(!mask) taking the first NMASK entries).
// ---------------------------------------------------------------------------
__global__ void find_positions_kernel(const void* __restrict__ mask_raw) {
    int b = threadIdx.x;
    if (b >= BS) return;
    const int is_byte = g_mask_is_byte;
    int cnt = 0;
    if (is_byte) {
        const unsigned char* row = (const unsigned char*)mask_raw + (size_t)b * SEQ;
        for (int s = 0; s < SEQ; s++) {
            if (row[s]) { if (cnt < NMASK) g_pos[b * NMASK + cnt] = s; cnt++; }
        }
    } else {
        const int* row = (const int*)mask_raw + (size_t)b * SEQ;
        for (int s = 0; s < SEQ; s++) {
            if (row[s]) { if (cnt < NMASK) g_pos[b * NMASK + cnt] = s; cnt++; }
        }
    }
}

// ---------------------------------------------------------------------------
// Kernel 2: one CTA per (b, j) item. Stream 32000 floats once:
//   - argmax with lowest-index tie-break
//   - gather log-prob at target index
// ---------------------------------------------------------------------------
__global__ __launch_bounds__(THREADS, 8)
void item_kernel(const float* __restrict__ output,
                 const void* __restrict__ target_raw) {
    const int item = blockIdx.x;            // 0..1279
    const int b    = item / NMASK;
    const int pos  = g_pos[item];
    const int tgt  = g_tgt_is_i64
                   ? (int)((const long long*)target_raw)[item]
                   : ((const int*)target_raw)[item];

    const float4* __restrict__ row =
        (const float4*)(output + ((size_t)b * SEQ + pos) * VOCAB);

    __shared__ float s_tlogp;
    __shared__ float s_val[THREADS];
    __shared__ int   s_idx[THREADS];

    const int tid = threadIdx.x;

    float best = -FLT_MAX;
    int   bidx = VOCAB;     // sentinel larger than any valid index
    float tlogp = 0.0f;
    bool  have_t = false;

    // 32000 floats = 8000 float4
    for (int v = tid; v < VOCAB / 4; v += THREADS) {
        float4 q = row[v];
        int base = v * 4;
        // increasing index with strict '>' keeps lowest index on ties
        if (q.x > best) { best = q.x; bidx = base + 0; }
        if (q.y > best) { best = q.y; bidx = base + 1; }
        if (q.z > best) { best = q.z; bidx = base + 2; }
        if (q.w > best) { best = q.w; bidx = base + 3; }
        if ((unsigned)(tgt - base) < 4u) {
            float e[4] = {q.x, q.y, q.z, q.w};
            tlogp = e[tgt - base];
            have_t = true;
        }
    }

    if (have_t) s_tlogp = tlogp;

    s_val[tid] = best;
    s_idx[tid] = bidx;
    __syncthreads();

    // tree reduction; tie-break: lower index wins
    for (int stride = THREADS / 2; stride > 0; stride >>= 1) {
        if (tid < stride) {
            float v2 = s_val[tid + stride];
            int   i2 = s_idx[tid + stride];
            if (v2 > s_val[tid] || (v2 == s_val[tid] && i2 < s_idx[tid])) {
                s_val[tid] = v2;
                s_idx[tid] = i2;
            }
        }
        __syncthreads();
    }

    if (tid == 0) {
        g_logp[item] = s_tlogp;
        g_corr[item] = (s_idx[0] == tgt) ? 1 : 0;
    }
}

// ---------------------------------------------------------------------------
// Kernel 3: deterministic final reduction over 1280 items.
// ---------------------------------------------------------------------------
__global__ void finalize_kernel(float* __restrict__ out, int out_size) {
    __shared__ float s_sum[THREADS];
    __shared__ int   s_cnt[THREADS];
    const int tid = threadIdx.x;

    float lsum = 0.0f;
    int   csum = 0;
    for (int i = tid; i < NITEMS; i += THREADS) {
        lsum += g_logp[i];
        csum += g_corr[i];
    }
    s_sum[tid] = lsum;
    s_cnt[tid] = csum;
    __syncthreads();

    for (int stride = THREADS / 2; stride > 0; stride >>= 1) {
        if (tid < stride) {
            s_sum[tid] += s_sum[tid + stride];
            s_cnt[tid] += s_cnt[tid + stride];
        }
        __syncthreads();
    }

    if (tid == 0) {
        const float inv = 1.0f / (float)(BS * NMASK);
        if (out_size > 0) out[0] = -s_sum[0] * inv;
        if (out_size > 1) out[1] = (float)s_cnt[0] * inv;
    }
}

extern "C" void kernel_launch(void* const* d_in, const int* in_sizes, int n_in,
                              void* d_out, int out_size) {
    const float* output = (const float*)d_in[0];
    const void*  target = d_in[1];
    const void*  mask   = d_in[2];
    float* out = (float*)d_out;

    detect_kernel<<<1, 256>>>((const unsigned char*)mask, (const int*)target);
    find_positions_kernel<<<1, 32>>>(mask);
    item_kernel<<<NITEMS, THREADS>>>(output, target);
    finalize_kernel<<<1, THREADS>>>(out, out_size);
}

// round 4
// speedup vs baseline: 2.0825x; 2.0825x over previous
#include <cuda_runtime.h>
#include <cuda_bf16.h>
#include <float.h>

#define BS 16
#define SEQ 512
#define VOCAB 32000
#define NV4 (VOCAB / 4)
#define NMASK 80
#define NITEMS (BS * NMASK)
#define THREADS 256

// Scratch (no device allocation allowed)
__device__ int      g_pos[NITEMS];     // masked positions, row-major (b, j)
__device__ float    g_logp[NITEMS];    // log-prob at target per item
__device__ int      g_corr[NITEMS];    // 1 if argmax == target
__device__ int      g_mask_is_byte;    // 1 if mask stored as 1-byte bool
__device__ int      g_tgt_is_i64;      // 1 if target stored as int64
__device__ unsigned g_done;            // completion counter for last-CTA reduce

// ---------------------------------------------------------------------------
// Kernel 1: layout detection + masked-position recovery (ballot scan, one
// warp per batch row; stable ascending order == stable argsort semantics).
// ---------------------------------------------------------------------------
__global__ void prep_kernel(const unsigned char* __restrict__ mask,
                            const int* __restrict__ target32) {
    __shared__ int s_byte, s_odd;
    const int tid = threadIdx.x;
    if (tid == 0) { s_byte = 0; s_odd = 0; g_done = 0; }
    __syncthreads();

    // mask: nonzero byte at offset %4 != 0 => byte-bool layout
    for (int i = tid; i < 2048; i += blockDim.x)
        if ((i & 3) != 0 && mask[i] != 0) atomicOr(&s_byte, 1);
    // target: all odd int32 words zero => int64 layout (targets < 32000)
    for (int i = tid; i < 128; i += blockDim.x)
        if (target32[2 * i + 1] != 0) atomicOr(&s_odd, 1);
    __syncthreads();

    if (tid == 0) {
        g_mask_is_byte = s_byte;
        g_tgt_is_i64   = s_odd ? 0 : 1;
    }

    const int w    = tid >> 5;   // warp -> batch row
    const int lane = tid & 31;
    if (w < BS) {
        const int is_byte = s_byte;
        int cnt = 0;
        for (int c = 0; c < SEQ / 32; c++) {
            const int s = c * 32 + lane;
            int m;
            if (is_byte) m = mask[(size_t)w * SEQ + s] != 0;
            else         m = ((const int*)mask)[(size_t)w * SEQ + s] != 0;
            unsigned bal = __ballot_sync(0xffffffffu, m);
            int pre = cnt + __popc(bal & ((1u << lane) - 1u));
            if (m && pre < NMASK) g_pos[w * NMASK + pre] = s;
            cnt += __popc(bal);
        }
    }
}

// ---------------------------------------------------------------------------
// per-element argmax / target-gather step (registers only, no local array)
// ---------------------------------------------------------------------------
__device__ __forceinline__ void step(float4 q, int base, int tgt,
                                     float& best, int& bidx,
                                     float& tlogp, bool& have_t) {
    if (q.x > best) { best = q.x; bidx = base + 0; }
    if (q.y > best) { best = q.y; bidx = base + 1; }
    if (q.z > best) { best = q.z; bidx = base + 2; }
    if (q.w > best) { best = q.w; bidx = base + 3; }
    const int off = tgt - base;
    if ((unsigned)off < 4u) {
        float t = (off == 0) ? q.x : (off == 1) ? q.y : (off == 2) ? q.z : q.w;
        tlogp = t;
        have_t = true;
    }
}

// ---------------------------------------------------------------------------
// Kernel 2: one CTA per (b, j) item. Stream 32000 floats once (MLP=8),
// argmax with lowest-index tie-break + target gather. Last CTA reduces.
// ---------------------------------------------------------------------------
__global__ __launch_bounds__(THREADS)
void item_kernel(const float* __restrict__ output,
                 const void* __restrict__ target_raw,
                 float* __restrict__ out, int out_size) {
    const int item = blockIdx.x;            // 0..1279
    const int b    = item / NMASK;
    const int pos  = g_pos[item];
    const int tgt  = g_tgt_is_i64
                   ? (int)((const long long*)target_raw)[item]
                   : ((const int*)target_raw)[item];

    const float4* __restrict__ row =
        (const float4*)(output + ((size_t)b * SEQ + pos) * VOCAB);

    __shared__ float s_tlogp;
    __shared__ float s_val[THREADS];
    __shared__ int   s_idx[THREADS];
    __shared__ int   s_last;

    const int tid = threadIdx.x;

    float best = -FLT_MAX;
    int   bidx = VOCAB;
    float tlogp = 0.0f;
    bool  have_t = false;

    int v = tid;
    // main: 8 independent float4 loads per batch (MLP=8)
    for (; v + 7 * THREADS < NV4; v += 8 * THREADS) {
        float4 q[8];
#pragma unroll
        for (int u = 0; u < 8; u++) q[u] = row[v + u * THREADS];
#pragma unroll
        for (int u = 0; u < 8; u++)
            step(q[u], (v + u * THREADS) * 4, tgt, best, bidx, tlogp, have_t);
    }
    // mid: 4-deep
    for (; v + 3 * THREADS < NV4; v += 4 * THREADS) {
        float4 q[4];
#pragma unroll
        for (int u = 0; u < 4; u++) q[u] = row[v + u * THREADS];
#pragma unroll
        for (int u = 0; u < 4; u++)
            step(q[u], (v + u * THREADS) * 4, tgt, best, bidx, tlogp, have_t);
    }
    // tail
    for (; v < NV4; v += THREADS) {
        float4 q = row[v];
        step(q, v * 4, tgt, best, bidx, tlogp, have_t);
    }

    if (have_t) s_tlogp = tlogp;
    s_val[tid] = best;
    s_idx[tid] = bidx;
    __syncthreads();

    // tree reduction; tie-break: lower index wins
    for (int stride = THREADS / 2; stride > 0; stride >>= 1) {
        if (tid < stride) {
            float v2 = s_val[tid + stride];
            int   i2 = s_idx[tid + stride];
            if (v2 > s_val[tid] || (v2 == s_val[tid] && i2 < s_idx[tid])) {
                s_val[tid] = v2;
                s_idx[tid] = i2;
            }
        }
        __syncthreads();
    }

    if (tid == 0) {
        g_logp[item] = s_tlogp;
        g_corr[item] = (s_idx[0] == tgt) ? 1 : 0;
        __threadfence();
        s_last = (atomicAdd(&g_done, 1u) == (unsigned)(NITEMS - 1));
    }
    __syncthreads();

    // last-arriving CTA performs the deterministic final reduction
    if (s_last) {
        __threadfence();
        float lsum = 0.0f;
        int   csum = 0;
        for (int i = tid; i < NITEMS; i += THREADS) {
            lsum += g_logp[i];
            csum += g_corr[i];
        }
        s_val[tid] = lsum;
        s_idx[tid] = csum;
        __syncthreads();
        for (int stride = THREADS / 2; stride > 0; stride >>= 1) {
            if (tid < stride) {
                s_val[tid] += s_val[tid + stride];
                s_idx[tid] += s_idx[tid + stride];
            }
            __syncthreads();
        }
        if (tid == 0) {
            const float inv = 1.0f / (float)NITEMS;
            if (out_size > 0) out[0] = -s_val[0] * inv;
            if (out_size > 1) out[1] = (float)s_idx[0] * inv;
        }
    }
}

extern "C" void kernel_launch(void* const* d_in, const int* in_sizes, int n_in,
                              void* d_out, int out_size) {
    const float* output = (const float*)d_in[0];
    const void*  target = d_in[1];
    const void*  mask   = d_in[2];
    float* out = (float*)d_out;

    prep_kernel<<<1, 512>>>((const unsigned char*)mask, (const int*)target);
    item_kernel<<<NITEMS, THREADS>>>(output, target, out, out_size);
}

// round 5
// speedup vs baseline: 2.2589x; 1.0847x over previous
#include <cuda_runtime.h>
#include <cuda_bf16.h>
#include <float.h>

#define BS 16
#define SEQ 512
#define VOCAB 32000
#define NV4 (VOCAB / 4)
#define NMASK 80
#define NITEMS (BS * NMASK)
#define THREADS 256

// Scratch (no device allocation allowed)
__device__ int      g_pos[NITEMS];     // masked positions, row-major (b, j)
__device__ float    g_logp[NITEMS];    // log-prob at target per item
__device__ int      g_corr[NITEMS];    // 1 if argmax == target
__device__ int      g_mask_is_byte;    // 1 if mask stored as 1-byte bool
__device__ int      g_tgt_is_i64;      // 1 if target stored as int64
__device__ unsigned g_done;            // completion counter for last-CTA reduce

// ---------------------------------------------------------------------------
// Kernel 1: layout detection + masked-position recovery (ballot scan, one
// warp per batch row; stable ascending order == stable argsort semantics).
// ---------------------------------------------------------------------------
__global__ void prep_kernel(const unsigned char* __restrict__ mask,
                            const int* __restrict__ target32) {
    __shared__ int s_byte, s_odd;
    const int tid = threadIdx.x;
    if (tid == 0) { s_byte = 0; s_odd = 0; g_done = 0; }
    __syncthreads();

    for (int i = tid; i < 2048; i += blockDim.x)
        if ((i & 3) != 0 && mask[i] != 0) atomicOr(&s_byte, 1);
    for (int i = tid; i < 128; i += blockDim.x)
        if (target32[2 * i + 1] != 0) atomicOr(&s_odd, 1);
    __syncthreads();

    if (tid == 0) {
        g_mask_is_byte = s_byte;
        g_tgt_is_i64   = s_odd ? 0 : 1;
    }

    const int w    = tid >> 5;   // warp -> batch row
    const int lane = tid & 31;
    if (w < BS) {
        const int is_byte = s_byte;
        int cnt = 0;
        for (int c = 0; c < SEQ / 32; c++) {
            const int s = c * 32 + lane;
            int m;
            if (is_byte) m = mask[(size_t)w * SEQ + s] != 0;
            else         m = ((const int*)mask)[(size_t)w * SEQ + s] != 0;
            unsigned bal = __ballot_sync(0xffffffffu, m);
            int pre = cnt + __popc(bal & ((1u << lane) - 1u));
            if (m && pre < NMASK) g_pos[w * NMASK + pre] = s;
            cnt += __popc(bal);
        }
    }
}

__device__ __forceinline__ float max4(float4 q) {
    return fmaxf(fmaxf(q.x, q.y), fmaxf(q.z, q.w));
}

// ---------------------------------------------------------------------------
// Kernel 2: one CTA per (b, j) item. Stream 32000 floats once (MLP=8).
// Argmax via per-batch fmaxf tree (no loop-carried dependency) + lazy
// lowest-index recovery on the rare strictly-greater update path.
// ---------------------------------------------------------------------------
__global__ __launch_bounds__(THREADS)
void item_kernel(const float* __restrict__ output,
                 const void* __restrict__ target_raw,
                 float* __restrict__ out, int out_size) {
    const int item = blockIdx.x;            // 0..1279
    const int b    = item / NMASK;
    const int pos  = g_pos[item];
    const int tgt  = g_tgt_is_i64
                   ? (int)((const long long*)target_raw)[item]
                   : ((const int*)target_raw)[item];

    const float* __restrict__ rowf =
        output + ((size_t)b * SEQ + pos) * VOCAB;
    const float4* __restrict__ row = (const float4*)rowf;

    __shared__ float s_tlogp;
    __shared__ float s_val[THREADS];
    __shared__ int   s_idx[THREADS];
    __shared__ int   s_last;

    const int tid = threadIdx.x;
    if (tid == 0) s_tlogp = __ldg(rowf + tgt);   // direct target gather

    float best = -FLT_MAX;
    int   bidx = VOCAB;

    int v = tid;
    // main: 8 independent float4 loads per iteration
    for (; v + 7 * THREADS < NV4; v += 8 * THREADS) {
        float4 q[8];
#pragma unroll
        for (int u = 0; u < 8; u++) q[u] = __ldcs(&row[v + u * THREADS]);

        // independent fmaxf tree over 32 values
        float m0 = fmaxf(max4(q[0]), max4(q[1]));
        float m1 = fmaxf(max4(q[2]), max4(q[3]));
        float m2 = fmaxf(max4(q[4]), max4(q[5]));
        float m3 = fmaxf(max4(q[6]), max4(q[7]));
        float m  = fmaxf(fmaxf(m0, m1), fmaxf(m2, m3));

        if (m > best) {      // rare: ~ln(8000) times per thread total
            best = m;
            // descending scan: last assignment == lowest index equal to m
#pragma unroll
            for (int u = 7; u >= 0; u--) {
                int base = (v + u * THREADS) * 4;
                if (q[u].w == m) bidx = base + 3;
                if (q[u].z == m) bidx = base + 2;
                if (q[u].y == m) bidx = base + 1;
                if (q[u].x == m) bidx = base + 0;
            }
        }
    }
    // mid: 4-deep
    for (; v + 3 * THREADS < NV4; v += 4 * THREADS) {
        float4 q[4];
#pragma unroll
        for (int u = 0; u < 4; u++) q[u] = __ldcs(&row[v + u * THREADS]);
        float m = fmaxf(fmaxf(max4(q[0]), max4(q[1])),
                        fmaxf(max4(q[2]), max4(q[3])));
        if (m > best) {
            best = m;
#pragma unroll
            for (int u = 3; u >= 0; u--) {
                int base = (v + u * THREADS) * 4;
                if (q[u].w == m) bidx = base + 3;
                if (q[u].z == m) bidx = base + 2;
                if (q[u].y == m) bidx = base + 1;
                if (q[u].x == m) bidx = base + 0;
            }
        }
    }
    // tail
    for (; v < NV4; v += THREADS) {
        float4 q = __ldcs(&row[v]);
        float m = max4(q);
        if (m > best) {
            best = m;
            int base = v * 4;
            if (q.w == m) bidx = base + 3;
            if (q.z == m) bidx = base + 2;
            if (q.y == m) bidx = base + 1;
            if (q.x == m) bidx = base + 0;
        }
    }

    s_val[tid] = best;
    s_idx[tid] = bidx;
    __syncthreads();

    // tree reduction; tie-break: lower index wins
    for (int stride = THREADS / 2; stride > 0; stride >>= 1) {
        if (tid < stride) {
            float v2 = s_val[tid + stride];
            int   i2 = s_idx[tid + stride];
            if (v2 > s_val[tid] || (v2 == s_val[tid] && i2 < s_idx[tid])) {
                s_val[tid] = v2;
                s_idx[tid] = i2;
            }
        }
        __syncthreads();
    }

    if (tid == 0) {
        g_logp[item] = s_tlogp;
        g_corr[item] = (s_idx[0] == tgt) ? 1 : 0;
        __threadfence();
        s_last = (atomicAdd(&g_done, 1u) == (unsigned)(NITEMS - 1));
    }
    __syncthreads();

    // last-arriving CTA performs the deterministic final reduction
    if (s_last) {
        __threadfence();
        float lsum = 0.0f;
        int   csum = 0;
        for (int i = tid; i < NITEMS; i += THREADS) {
            lsum += g_logp[i];
            csum += g_corr[i];
        }
        s_val[tid] = lsum;
        s_idx[tid] = csum;
        __syncthreads();
        for (int stride = THREADS / 2; stride > 0; stride >>= 1) {
            if (tid < stride) {
                s_val[tid] += s_val[tid + stride];
                s_idx[tid] += s_idx[tid + stride];
            }
            __syncthreads();
        }
        if (tid == 0) {
            const float inv = 1.0f / (float)NITEMS;
            if (out_size > 0) out[0] = -s_val[0] * inv;
            if (out_size > 1) out[1] = (float)s_idx[0] * inv;
        }
    }
}

extern "C" void kernel_launch(void* const* d_in, const int* in_sizes, int n_in,
                              void* d_out, int out_size) {
    const float* output = (const float*)d_in[0];
    const void*  target = d_in[1];
    const void*  mask   = d_in[2];
    float* out = (float*)d_out;

    prep_kernel<<<1, 512>>>((const unsigned char*)mask, (const int*)target);
    item_kernel<<<NITEMS, THREADS>>>(output, target, out, out_size);
}